// round 1
// baseline (speedup 1.0000x reference)
#include <cuda_runtime.h>

#define B_ 8
#define N_ 1024
#define C_ 64

// Scratch for Chebyshev recurrence (allocation-free rule -> __device__ globals)
__device__ float g_Z1[B_ * N_ * C_];
__device__ float g_Z2[B_ * N_ * C_];
__device__ float g_Z3[B_ * N_ * C_];

// Shared layout (bytes):
//   main loop:  Ls[16][68] (transposed L tile), Bs[16][68]
//   epilogue :  Zs[64][68], Th[64][64]
// max = 64*68*4 + 64*64*4 = 33792 B  (< 48KB static)
#define SMEM_FLOATS 8448

__device__ __forceinline__ void theta_accum(const float* Zs, const float* Th,
                                            int trow, int tcol, float o[4][4]) {
    #pragma unroll 8
    for (int c = 0; c < 64; c++) {
        float a0 = Zs[(trow + 0) * 68 + c];
        float a1 = Zs[(trow + 1) * 68 + c];
        float a2 = Zs[(trow + 2) * 68 + c];
        float a3 = Zs[(trow + 3) * 68 + c];
        float4 t = *(const float4*)&Th[c * 64 + tcol];
        o[0][0] += a0 * t.x; o[0][1] += a0 * t.y; o[0][2] += a0 * t.z; o[0][3] += a0 * t.w;
        o[1][0] += a1 * t.x; o[1][1] += a1 * t.y; o[1][2] += a1 * t.z; o[1][3] += a1 * t.w;
        o[2][0] += a2 * t.x; o[2][1] += a2 * t.y; o[2][2] += a2 * t.z; o[2][3] += a2 * t.w;
        o[3][0] += a3 * t.x; o[3][1] += a3 * t.y; o[3][2] += a3 * t.z; o[3][3] += a3 * t.w;
    }
}

// One Chebyshev pass for rows [m0, m0+64) of batch b:
//   C      = L[b] @ Bin[b]            (64 x 64 tile, K = 1024)
//   Znext  = alpha*C - (FIRST ? 0 : Sub)
//   Zout   = Znext
//   out    = (FIRST ? x@th0 + Znext@thK : out + Znext@thK)
template <bool FIRST>
__global__ __launch_bounds__(256)
void cheb_pass(const float* __restrict__ L,
               const float* __restrict__ Bin,
               const float* __restrict__ Sub,
               const float* __restrict__ x,
               const float* __restrict__ thK,
               const float* __restrict__ th0,
               float* __restrict__ Zout,
               float* __restrict__ out,
               float alpha) {
    __shared__ __align__(16) float sraw[SMEM_FLOATS];
    float* Ls = sraw;              // [16][68], Ls[k][m] (transposed)
    float* Bs = sraw + 16 * 68;    // [16][68], Bs[k][n]

    const int tid  = threadIdx.x;
    const int b    = blockIdx.y;
    const int m0   = blockIdx.x * 64;

    const int trow = (tid >> 4) * 4;   // 0..60
    const int tcol = (tid & 15) * 4;   // 0..60

    const int lr = tid >> 2;           // 0..63   (L row within tile)
    const int lk = (tid & 3) * 4;      // 0,4,8,12 (k offset within chunk)
    const int bk = tid >> 4;           // 0..15   (B k within chunk)
    const int bn = (tid & 15) * 4;     // 0..60

    const float* Lb = L   + ((size_t)b * N_ + m0) * N_;
    const float* Bb = Bin + (size_t)b * N_ * C_;

    float acc[4][4];
    #pragma unroll
    for (int i = 0; i < 4; i++)
        #pragma unroll
        for (int j = 0; j < 4; j++) acc[i][j] = 0.f;

    // ---- main GEMM loop: C = L @ Bin, K = 1024 in chunks of 16 ----
    float4 rL = *(const float4*)(Lb + (size_t)lr * N_ + lk);
    float4 rB = *(const float4*)(Bb + (size_t)bk * C_ + bn);

    Ls[(lk + 0) * 68 + lr] = rL.x;
    Ls[(lk + 1) * 68 + lr] = rL.y;
    Ls[(lk + 2) * 68 + lr] = rL.z;
    Ls[(lk + 3) * 68 + lr] = rL.w;
    *(float4*)&Bs[bk * 68 + bn] = rB;
    __syncthreads();

    const int NCH = N_ / 16;  // 64
    for (int ch = 0; ch < NCH; ch++) {
        if (ch + 1 < NCH) {
            const int k0 = (ch + 1) * 16;
            rL = *(const float4*)(Lb + (size_t)lr * N_ + k0 + lk);
            rB = *(const float4*)(Bb + (size_t)(k0 + bk) * C_ + bn);
        }
        #pragma unroll
        for (int kk = 0; kk < 16; kk++) {
            float4 a = *(const float4*)&Ls[kk * 68 + trow];
            float4 v = *(const float4*)&Bs[kk * 68 + tcol];
            acc[0][0] += a.x * v.x; acc[0][1] += a.x * v.y; acc[0][2] += a.x * v.z; acc[0][3] += a.x * v.w;
            acc[1][0] += a.y * v.x; acc[1][1] += a.y * v.y; acc[1][2] += a.y * v.z; acc[1][3] += a.y * v.w;
            acc[2][0] += a.z * v.x; acc[2][1] += a.z * v.y; acc[2][2] += a.z * v.z; acc[2][3] += a.z * v.w;
            acc[3][0] += a.w * v.x; acc[3][1] += a.w * v.y; acc[3][2] += a.w * v.z; acc[3][3] += a.w * v.w;
        }
        __syncthreads();
        if (ch + 1 < NCH) {
            Ls[(lk + 0) * 68 + lr] = rL.x;
            Ls[(lk + 1) * 68 + lr] = rL.y;
            Ls[(lk + 2) * 68 + lr] = rL.z;
            Ls[(lk + 3) * 68 + lr] = rL.w;
            *(float4*)&Bs[bk * 68 + bn] = rB;
        }
        __syncthreads();
    }

    // ---- Znext = alpha*C - Sub ; write to Zout ----
    float zn[4][4];
    if (FIRST) {
        #pragma unroll
        for (int i = 0; i < 4; i++)
            #pragma unroll
            for (int j = 0; j < 4; j++) zn[i][j] = acc[i][j];
    } else {
        const float* Sb = Sub + ((size_t)b * N_ + m0) * C_;
        #pragma unroll
        for (int i = 0; i < 4; i++) {
            float4 s = *(const float4*)(Sb + (size_t)(trow + i) * C_ + tcol);
            zn[i][0] = alpha * acc[i][0] - s.x;
            zn[i][1] = alpha * acc[i][1] - s.y;
            zn[i][2] = alpha * acc[i][2] - s.z;
            zn[i][3] = alpha * acc[i][3] - s.w;
        }
    }
    {
        float* Zo = Zout + ((size_t)b * N_ + m0) * C_;
        #pragma unroll
        for (int i = 0; i < 4; i++) {
            float4 z = make_float4(zn[i][0], zn[i][1], zn[i][2], zn[i][3]);
            *(float4*)(Zo + (size_t)(trow + i) * C_ + tcol) = z;
        }
    }

    // ---- epilogue: out (+)= Znext @ thK  [+ x @ th0 when FIRST] ----
    float* Zs = sraw;            // [64][68]
    float* Th = sraw + 64 * 68;  // [64][64]

    #pragma unroll
    for (int i = 0; i < 4; i++) {
        float4 z = make_float4(zn[i][0], zn[i][1], zn[i][2], zn[i][3]);
        *(float4*)&Zs[(trow + i) * 68 + tcol] = z;
    }
    #pragma unroll
    for (int i = 0; i < 4; i++) {
        const int idx = i * 1024 + tid * 4;
        *(float4*)&Th[idx] = *(const float4*)(thK + idx);
    }
    __syncthreads();

    float o[4][4];
    #pragma unroll
    for (int i = 0; i < 4; i++)
        #pragma unroll
        for (int j = 0; j < 4; j++) o[i][j] = 0.f;

    theta_accum(Zs, Th, trow, tcol, o);

    if (FIRST) {
        __syncthreads();
        // stage x tile into Zs, th0 into Th
        const float* xb = x + ((size_t)b * N_ + m0) * C_;
        const int xr = tid >> 2;
        const int xc = (tid & 3) * 16;
        #pragma unroll
        for (int q = 0; q < 4; q++) {
            float4 v = *(const float4*)(xb + (size_t)xr * C_ + xc + q * 4);
            *(float4*)&Zs[xr * 68 + xc + q * 4] = v;
        }
        #pragma unroll
        for (int i = 0; i < 4; i++) {
            const int idx = i * 1024 + tid * 4;
            *(float4*)&Th[idx] = *(const float4*)(th0 + idx);
        }
        __syncthreads();
        theta_accum(Zs, Th, trow, tcol, o);
    }

    float* ob = out + ((size_t)b * N_ + m0) * C_;
    #pragma unroll
    for (int i = 0; i < 4; i++) {
        float4 v = make_float4(o[i][0], o[i][1], o[i][2], o[i][3]);
        if (!FIRST) {
            float4 cur = *(const float4*)(ob + (size_t)(trow + i) * C_ + tcol);
            v.x += cur.x; v.y += cur.y; v.z += cur.z; v.w += cur.w;
        }
        *(float4*)(ob + (size_t)(trow + i) * C_ + tcol) = v;
    }
}

extern "C" void kernel_launch(void* const* d_in, const int* in_sizes, int n_in,
                              void* d_out, int out_size) {
    (void)in_sizes; (void)n_in; (void)out_size;
    const float* x  = (const float*)d_in[0];   // [8,1024,64]
    const float* L  = (const float*)d_in[1];   // [8,1024,1024]
    const float* th = (const float*)d_in[2];   // [4,64,64]
    float* out = (float*)d_out;                // [8,1024,64]

    float *z1, *z2, *z3;
    cudaGetSymbolAddress((void**)&z1, g_Z1);
    cudaGetSymbolAddress((void**)&z2, g_Z2);
    cudaGetSymbolAddress((void**)&z3, g_Z3);

    dim3 grid(N_ / 64, B_);
    dim3 block(256);

    // Z1 = L x           ; out  = x@th0 + Z1@th1
    cheb_pass<true ><<<grid, block>>>(L, x,  nullptr, x, th + 1 * 4096, th, z1, out, 1.0f);
    // Z2 = 2 L Z1 - x    ; out += Z2@th2
    cheb_pass<false><<<grid, block>>>(L, z1, x,  nullptr, th + 2 * 4096, nullptr, z2, out, 2.0f);
    // Z3 = 2 L Z2 - Z1   ; out += Z3@th3
    cheb_pass<false><<<grid, block>>>(L, z2, z1, nullptr, th + 3 * 4096, nullptr, z3, out, 2.0f);
}